// round 1
// baseline (speedup 1.0000x reference)
#include <cuda_runtime.h>
#include <math.h>

// Problem dims
#define BB 256
#define II 1152
#define PP 8
#define JJ 10
#define DD 16
#define JD 160   // JJ*DD

// Scratch (device globals; no runtime allocation allowed)
__device__ float g_votes[(size_t)BB * II * JD];   // 189 MB
__device__ float g_blog [(size_t)BB * II * JJ];   // 11.8 MB
__device__ float g_s[3][BB * JD];                 // per-iteration s accumulators
__device__ float g_v[2][BB * JD];                 // v0, v1

// ---------------------------------------------------------------------------
// Zero the three s accumulators (must happen every launch; graph replays).
// ---------------------------------------------------------------------------
__global__ void zero_kernel() {
    int t = blockIdx.x * blockDim.x + threadIdx.x;
    if (t < 3 * BB * JD) ((float*)g_s)[t] = 0.0f;
}

// ---------------------------------------------------------------------------
// votes[b,i,j,d] = sum_p W[i,j,d,p] * x[b,i,p]
// Grid: 144 CTAs (I/8), 256 threads. Warp w owns i = blk*8+w.
// Lane owns jd = lane + 32k (k=0..4); its 40 W values live in registers and
// are reused across all 256 batches -> W is read from HBM exactly once.
// ---------------------------------------------------------------------------
__global__ __launch_bounds__(256) void votes_kernel(const float* __restrict__ x,
                                                    const float* __restrict__ W) {
    int wid  = threadIdx.x >> 5;
    int lane = threadIdx.x & 31;
    int i = blockIdx.x * 8 + wid;

    const float4* Wp = (const float4*)(W + (size_t)i * (JJ * DD * PP));
    float4 wv0[5], wv1[5];
#pragma unroll
    for (int k = 0; k < 5; k++) {
        int jd = lane + 32 * k;
        wv0[k] = Wp[jd * 2 + 0];
        wv1[k] = Wp[jd * 2 + 1];
    }

    for (int b = 0; b < BB; b++) {
        const float4* xp = (const float4*)(x + ((size_t)b * II + i) * PP);
        float4 x0 = __ldg(xp + 0);   // warp-broadcast
        float4 x1 = __ldg(xp + 1);
        float* vout = g_votes + ((size_t)b * II + i) * JD;
#pragma unroll
        for (int k = 0; k < 5; k++) {
            float acc =
                fmaf(wv0[k].x, x0.x,
                fmaf(wv0[k].y, x0.y,
                fmaf(wv0[k].z, x0.z,
                fmaf(wv0[k].w, x0.w,
                fmaf(wv1[k].x, x1.x,
                fmaf(wv1[k].y, x1.y,
                fmaf(wv1[k].z, x1.z, wv1[k].w * x1.w)))))));
            vout[lane + 32 * k] = acc;   // coalesced 128B per k per warp
        }
    }
}

// ---------------------------------------------------------------------------
// One routing pass (single read of votes):
//   MODE 0: c = 1/10 (softmax of zeros), accumulate s0.
//   MODE 1: bnew = votes . v0 ; write g_blog ; c = softmax(bnew) ; s1.
//   MODE 2: bnew = g_blog + votes . v1 ; c = softmax(bnew) ; s2.
// Grid (8, 256): blockIdx.y = b, blockIdx.x = i-chunk of 144.
// 256 threads; each warp handles 18 i's, 3 at a time:
// lane -> (i_sub = lane/10 clamped, j = lane%10). Lanes 30/31 duplicate work
// (never sourced in reductions, stores gated).
// ---------------------------------------------------------------------------
template <int MODE>
__global__ __launch_bounds__(256) void route_kernel(const float* __restrict__ vprev) {
    __shared__ float s_acc[JD];

    int b     = blockIdx.y;
    int chunk = blockIdx.x;
    int tid   = threadIdx.x;
    int wid   = tid >> 5;
    int lane  = tid & 31;

    int i_sub = lane / 10; if (i_sub > 2) i_sub = 2;
    int j     = lane % 10;
    bool valid = (lane < 30);

    // v_prev row for this lane's digit capsule: fixed across the whole i loop.
    float vp[DD];
    if (MODE != 0) {
        const float4* vpp = (const float4*)(vprev + b * JD + j * DD);
#pragma unroll
        for (int q = 0; q < 4; q++) {
            float4 t = vpp[q];
            vp[4*q+0] = t.x; vp[4*q+1] = t.y; vp[4*q+2] = t.z; vp[4*q+3] = t.w;
        }
    }

    if (tid < JD) s_acc[tid] = 0.0f;
    __syncthreads();

    float sacc[DD];
#pragma unroll
    for (int d = 0; d < DD; d++) sacc[d] = 0.0f;

    int i0 = chunk * 144 + wid * 18;
    for (int t = 0; t < 18; t += 3) {
        int i = i0 + t + i_sub;
        const float4* vt4 = (const float4*)(g_votes + ((size_t)b * II + i) * JD + j * DD);
        float vt[DD];
#pragma unroll
        for (int q = 0; q < 4; q++) {
            float4 a = vt4[q];
            vt[4*q+0] = a.x; vt[4*q+1] = a.y; vt[4*q+2] = a.z; vt[4*q+3] = a.w;
        }

        float c;
        if (MODE == 0) {
            c = 0.1f;
        } else {
            float dot = 0.0f;
#pragma unroll
            for (int d = 0; d < DD; d++) dot = fmaf(vt[d], vp[d], dot);
            float bnew = dot;
            if (MODE == 2) bnew += g_blog[((size_t)b * II + i) * JJ + j];
            if (MODE == 1 && valid) g_blog[((size_t)b * II + i) * JJ + j] = bnew;

            // softmax over the 10 digit capsules (lanes i_sub*10 .. i_sub*10+9)
            float m = bnew;
#pragma unroll
            for (int jj = 0; jj < 10; jj++)
                m = fmaxf(m, __shfl_sync(0xffffffffu, bnew, i_sub * 10 + jj));
            float e = expf(bnew - m);
            float ssum = 0.0f;
#pragma unroll
            for (int jj = 0; jj < 10; jj++)
                ssum += __shfl_sync(0xffffffffu, e, i_sub * 10 + jj);
            c = e / ssum;
        }
#pragma unroll
        for (int d = 0; d < DD; d++) sacc[d] = fmaf(c, vt[d], sacc[d]);
    }

    // Reduce the 3 i_sub copies down to lanes 0..9 (lanes 30/31 never sourced).
#pragma unroll
    for (int d = 0; d < DD; d++) {
        float v1 = __shfl_sync(0xffffffffu, sacc[d], lane + 10);
        float v2 = __shfl_sync(0xffffffffu, sacc[d], lane + 20);
        sacc[d] += v1 + v2;
    }
    if (lane < 10) {
#pragma unroll
        for (int d = 0; d < DD; d++)
            atomicAdd(&s_acc[j * DD + d], sacc[d]);
    }
    __syncthreads();
    if (tid < JD)
        atomicAdd(&g_s[MODE][b * JD + tid], s_acc[tid]);
}

// ---------------------------------------------------------------------------
// squash: v = s * (||s||^2 / (1+||s||^2) / sqrt(||s||^2 + eps))
// One thread per (b, j) capsule.
// ---------------------------------------------------------------------------
__global__ void squash_kernel(const float* __restrict__ s, float* __restrict__ out) {
    int t = blockIdx.x * blockDim.x + threadIdx.x;
    if (t >= BB * JJ) return;
    const float* sp = s + t * DD;
    float v[DD];
    float s2 = 0.0f;
#pragma unroll
    for (int d = 0; d < DD; d++) { v[d] = sp[d]; s2 = fmaf(v[d], v[d], s2); }
    float scale = s2 / (1.0f + s2) / sqrtf(s2 + 1e-7f);
#pragma unroll
    for (int d = 0; d < DD; d++) out[t * DD + d] = v[d] * scale;
}

// ---------------------------------------------------------------------------
extern "C" void kernel_launch(void* const* d_in, const int* in_sizes, int n_in,
                              void* d_out, int out_size) {
    const float* x = (const float*)d_in[0];   // [256,1152,8]
    const float* W = (const float*)d_in[1];   // [1152,10,16,8]
    float* out = (float*)d_out;               // [256,10,16]

    float *gs = nullptr, *gv = nullptr;
    cudaGetSymbolAddress((void**)&gs, g_s);
    cudaGetSymbolAddress((void**)&gv, g_v);

    dim3 rgrid(8, BB);

    zero_kernel<<<(3 * BB * JD + 255) / 256, 256>>>();
    votes_kernel<<<II / 8, 256>>>(x, W);

    // iter 0: uniform coupling
    route_kernel<0><<<rgrid, 256>>>(nullptr);
    squash_kernel<<<(BB * JJ + 255) / 256, 256>>>(gs + 0 * BB * JD, gv + 0 * BB * JD);

    // iter 1: b1 = votes.v0
    route_kernel<1><<<rgrid, 256>>>(gv + 0 * BB * JD);
    squash_kernel<<<(BB * JJ + 255) / 256, 256>>>(gs + 1 * BB * JD, gv + 1 * BB * JD);

    // iter 2: b2 = b1 + votes.v1 ; final v -> d_out
    route_kernel<2><<<rgrid, 256>>>(gv + 1 * BB * JD);
    squash_kernel<<<(BB * JJ + 255) / 256, 256>>>(gs + 2 * BB * JD, out);
}

// round 2
// speedup vs baseline: 1.8063x; 1.8063x over previous
#include <cuda_runtime.h>
#include <cuda_fp16.h>
#include <math.h>

// Problem dims
#define BB 256
#define II 1152
#define PP 8
#define JJ 10
#define DD 16
#define JD 160   // JJ*DD

// Scratch (device globals; no runtime allocation allowed)
__device__ __half g_votes[(size_t)BB * II * JD];  // 94.4 MB, fp16
__device__ float  g_s[3][BB * JD];                // per-iteration s accumulators

// ---------------------------------------------------------------------------
// Zero the three s accumulators (graph replays -> must re-zero each launch).
// ---------------------------------------------------------------------------
__global__ void zero_kernel() {
    int t = blockIdx.x * blockDim.x + threadIdx.x;
    if (t < 3 * BB * JD) ((float*)g_s)[t] = 0.0f;
}

// ---------------------------------------------------------------------------
// votes[b,i,jd] = sum_p W[i,jd,p] * x[b,i,p], stored fp16.
// Grid (144, 8): x = i-block of 8, y = batch-group of 32.
// Warp w owns i = bx*8+w; lane owns jd = lane+32k (k=0..4), W in registers.
// Batch loop software-pipelined (prefetch next x while computing).
// ---------------------------------------------------------------------------
__global__ __launch_bounds__(256) void votes_kernel(const float* __restrict__ x,
                                                    const float* __restrict__ W) {
    int wid  = threadIdx.x >> 5;
    int lane = threadIdx.x & 31;
    int i    = blockIdx.x * 8 + wid;
    int b0   = blockIdx.y * 32;

    const float4* Wp = (const float4*)(W + (size_t)i * (JJ * DD * PP));
    float4 wv0[5], wv1[5];
#pragma unroll
    for (int k = 0; k < 5; k++) {
        int jd = lane + 32 * k;
        wv0[k] = Wp[jd * 2 + 0];
        wv1[k] = Wp[jd * 2 + 1];
    }

    const float4* xp = (const float4*)(x + ((size_t)b0 * II + i) * PP);
    float4 x0 = __ldg(xp + 0);
    float4 x1 = __ldg(xp + 1);

    for (int bi = 0; bi < 32; bi++) {
        float4 nx0, nx1;
        if (bi < 31) {
            const float4* nxp = (const float4*)(x + ((size_t)(b0 + bi + 1) * II + i) * PP);
            nx0 = __ldg(nxp + 0);
            nx1 = __ldg(nxp + 1);
        }
        __half* vout = g_votes + ((size_t)(b0 + bi) * II + i) * JD;
#pragma unroll
        for (int k = 0; k < 5; k++) {
            float acc =
                fmaf(wv0[k].x, x0.x,
                fmaf(wv0[k].y, x0.y,
                fmaf(wv0[k].z, x0.z,
                fmaf(wv0[k].w, x0.w,
                fmaf(wv1[k].x, x1.x,
                fmaf(wv1[k].y, x1.y,
                fmaf(wv1[k].z, x1.z, wv1[k].w * x1.w)))))));
            vout[lane + 32 * k] = __float2half_rn(acc);  // 64B/warp per k
        }
        x0 = nx0; x1 = nx1;
    }
}

// ---------------------------------------------------------------------------
// One routing pass, single read of votes, squash of previous s fused in:
//   MODE 0: c = 1/10, accumulate s0.
//   MODE 1: v0 = squash(s0); c = softmax_j(votes.v0); accumulate s1.
//   MODE 2: vsum = squash(s0)+squash(s1); c = softmax_j(votes.vsum); s2.
//   (b0 = 0 so b2 = votes.v0 + votes.v1 = votes.(v0+v1) — no logit storage.)
// Grid (8, 256): x = i-chunk of 144, y = batch. 256 threads.
// lane -> (i_sub = min(lane/10,2), j = lane%10); lanes 30/31 duplicate work
// and are never sourced in reductions.
// ---------------------------------------------------------------------------
template <int MODE>
__global__ __launch_bounds__(256) void route_kernel() {
    __shared__ float s_acc[JD];
    __shared__ float sm_s[JD];
    __shared__ float vp_s[JD];

    int b     = blockIdx.y;
    int chunk = blockIdx.x;
    int tid   = threadIdx.x;
    int wid   = tid >> 5;
    int lane  = tid & 31;

    int i_sub = lane / 10; if (i_sub > 2) i_sub = 2;
    int j     = lane % 10;

    if (tid < JD) s_acc[tid] = 0.0f;

    // ---- inline squash of previous iteration's s (per this CTA's batch) ----
    if (MODE != 0) {
        if (tid < JD) sm_s[tid] = g_s[0 + (MODE == 2 ? 0 : MODE - 1)][b * JD + tid];
        // MODE1 uses s0; MODE2 starts with s0 then adds squash(s1).
        __syncthreads();
        if (tid < JD) {
            int jj = tid >> 4;
            float s2 = 0.0f;
#pragma unroll
            for (int d = 0; d < DD; d++) {
                float t = sm_s[jj * DD + d];
                s2 = fmaf(t, t, s2);
            }
            float sc = s2 / (1.0f + s2) / sqrtf(s2 + 1e-7f);
            vp_s[tid] = sm_s[tid] * sc;
        }
        if (MODE == 2) {
            __syncthreads();
            if (tid < JD) sm_s[tid] = g_s[1][b * JD + tid];
            __syncthreads();
            if (tid < JD) {
                int jj = tid >> 4;
                float s2 = 0.0f;
#pragma unroll
                for (int d = 0; d < DD; d++) {
                    float t = sm_s[jj * DD + d];
                    s2 = fmaf(t, t, s2);
                }
                float sc = s2 / (1.0f + s2) / sqrtf(s2 + 1e-7f);
                vp_s[tid] += sm_s[tid] * sc;
            }
        }
    }
    __syncthreads();

    float vp[DD];
    if (MODE != 0) {
#pragma unroll
        for (int d = 0; d < DD; d++) vp[d] = vp_s[j * DD + d];  // broadcast LDS
    }

    float sacc[DD];
#pragma unroll
    for (int d = 0; d < DD; d++) sacc[d] = 0.0f;

    int i0 = chunk * 144 + wid * 18;
    for (int t = 0; t < 18; t += 3) {
        int i = i0 + t + i_sub;
        const uint4* vt16 = (const uint4*)(g_votes + ((size_t)b * II + i) * JD + j * DD);
        uint4 a0 = vt16[0];
        uint4 a1 = vt16[1];
        float vt[DD];
        {
            const __half2* h0 = (const __half2*)&a0;
            const __half2* h1 = (const __half2*)&a1;
#pragma unroll
            for (int q = 0; q < 4; q++) {
                float2 f0 = __half22float2(h0[q]);
                float2 f1 = __half22float2(h1[q]);
                vt[2 * q + 0] = f0.x; vt[2 * q + 1] = f0.y;
                vt[8 + 2 * q + 0] = f1.x; vt[8 + 2 * q + 1] = f1.y;
            }
        }

        float c;
        if (MODE == 0) {
            c = 0.1f;
        } else {
            float dot = 0.0f;
#pragma unroll
            for (int d = 0; d < DD; d++) dot = fmaf(vt[d], vp[d], dot);
            float bnew = dot;
            // softmax over the 10 digit capsules (lanes i_sub*10 .. +9)
            float m = bnew;
#pragma unroll
            for (int jj = 0; jj < 10; jj++)
                m = fmaxf(m, __shfl_sync(0xffffffffu, bnew, i_sub * 10 + jj));
            float e = expf(bnew - m);
            float ssum = 0.0f;
#pragma unroll
            for (int jj = 0; jj < 10; jj++)
                ssum += __shfl_sync(0xffffffffu, e, i_sub * 10 + jj);
            c = e / ssum;
        }
#pragma unroll
        for (int d = 0; d < DD; d++) sacc[d] = fmaf(c, vt[d], sacc[d]);
    }

    // fold the 3 i_sub copies into lanes 0..9 (lanes 30/31 never sourced)
#pragma unroll
    for (int d = 0; d < DD; d++) {
        float v1 = __shfl_sync(0xffffffffu, sacc[d], lane + 10);
        float v2 = __shfl_sync(0xffffffffu, sacc[d], lane + 20);
        sacc[d] += v1 + v2;
    }
    if (lane < 10) {
#pragma unroll
        for (int d = 0; d < DD; d++)
            atomicAdd(&s_acc[j * DD + d], sacc[d]);
    }
    __syncthreads();
    if (tid < JD)
        atomicAdd(&g_s[MODE][b * JD + tid], s_acc[tid]);
}

// ---------------------------------------------------------------------------
// Final squash: v = s * (||s||^2/(1+||s||^2)/sqrt(||s||^2+eps)) -> d_out
// ---------------------------------------------------------------------------
__global__ void squash_kernel(const float* __restrict__ s, float* __restrict__ out) {
    int t = blockIdx.x * blockDim.x + threadIdx.x;
    if (t >= BB * JJ) return;
    const float* sp = s + t * DD;
    float v[DD];
    float s2 = 0.0f;
#pragma unroll
    for (int d = 0; d < DD; d++) { v[d] = sp[d]; s2 = fmaf(v[d], v[d], s2); }
    float scale = s2 / (1.0f + s2) / sqrtf(s2 + 1e-7f);
#pragma unroll
    for (int d = 0; d < DD; d++) out[t * DD + d] = v[d] * scale;
}

// ---------------------------------------------------------------------------
extern "C" void kernel_launch(void* const* d_in, const int* in_sizes, int n_in,
                              void* d_out, int out_size) {
    const float* x = (const float*)d_in[0];   // [256,1152,8]
    const float* W = (const float*)d_in[1];   // [1152,10,16,8]
    float* out = (float*)d_out;               // [256,10,16]

    float* gs = nullptr;
    cudaGetSymbolAddress((void**)&gs, g_s);

    dim3 vgrid(II / 8, 8);
    dim3 rgrid(8, BB);

    zero_kernel<<<(3 * BB * JD + 255) / 256, 256>>>();
    votes_kernel<<<vgrid, 256>>>(x, W);

    route_kernel<0><<<rgrid, 256>>>();
    route_kernel<1><<<rgrid, 256>>>();
    route_kernel<2><<<rgrid, 256>>>();

    squash_kernel<<<(BB * JJ + 255) / 256, 256>>>(gs + 2 * BB * JD, out);
}

// round 5
// speedup vs baseline: 2.4428x; 1.3524x over previous
#include <cuda_runtime.h>
#include <cuda_fp16.h>
#include <math.h>

// Problem dims
#define BB 256
#define II 1152
#define PP 8
#define JJ 10
#define DD 16
#define JD 160   // JJ*DD

// Route-kernel tiling
#define CI 128            // i's per route CTA
#define NCHUNK (II / CI)  // 9
#define VS 168            // smem half-stride per i row (16B aligned, avoids conflicts)

// Scratch (device globals; no runtime allocation allowed)
__device__ __half g_votes[(size_t)BB * II * JD];  // 94.4 MB fp16
__device__ float  g_s[3][BB * JD];                // s0, s1, s2 accumulators

// 32-byte vector for 256-bit loads (ulonglong4 is deprecated on CUDA 13)
struct __align__(32) u64x4 { unsigned long long x, y, z, w; };

// ---------------------------------------------------------------------------
// L2 eviction-priority hinted 256-bit loads (sm_103 ptxas requires v4.b64 /
// v8.b32 width for any L2::evict_* modifier). One (i,j) fp16 vote row = 32 B.
// ---------------------------------------------------------------------------
__device__ __forceinline__ u64x4 ldg256_el(const u64x4* p) {
    u64x4 v;
    asm volatile("ld.global.nc.L2::evict_last.v4.u64 {%0,%1,%2,%3}, [%4];"
                 : "=l"(v.x), "=l"(v.y), "=l"(v.z), "=l"(v.w) : "l"(p));
    return v;
}
__device__ __forceinline__ u64x4 ldg256_ef(const u64x4* p) {
    u64x4 v;
    asm volatile("ld.global.nc.L2::evict_first.v4.u64 {%0,%1,%2,%3}, [%4];"
                 : "=l"(v.x), "=l"(v.y), "=l"(v.z), "=l"(v.w) : "l"(p));
    return v;
}

// ---------------------------------------------------------------------------
// Zero s accumulators (graph replays -> re-zero every launch).
// ---------------------------------------------------------------------------
__global__ void zero_kernel() {
    int t = blockIdx.x * blockDim.x + threadIdx.x;
    if (t < 3 * BB * JD) ((float*)g_s)[t] = 0.0f;
}

// ---------------------------------------------------------------------------
// votes[b,i,jd] = sum_p W[i,jd,p] * x[b,i,p], stored fp16.
// Fuses iteration-0 routing: s0[b,jd] = 0.1 * sum_i votes[b,i,jd]
// (softmax of zero logits -> c = 1/10) via CTA smem reduce + global atomics.
// Grid (144, 8): x = i-block of 8 (warp per i), y = batch-group of 32.
// ---------------------------------------------------------------------------
__global__ __launch_bounds__(256) void votes_kernel(const float* __restrict__ x,
                                                    const float* __restrict__ W) {
    __shared__ float s_part[8][JD];

    int wid  = threadIdx.x >> 5;
    int lane = threadIdx.x & 31;
    int i    = blockIdx.x * 8 + wid;
    int b0   = blockIdx.y * 32;

    const float4* Wp = (const float4*)(W + (size_t)i * (JD * PP));
    float4 wv0[5], wv1[5];
#pragma unroll
    for (int k = 0; k < 5; k++) {
        int jd = lane + 32 * k;
        wv0[k] = Wp[jd * 2 + 0];
        wv1[k] = Wp[jd * 2 + 1];
    }

    const float4* xp = (const float4*)(x + ((size_t)b0 * II + i) * PP);
    float4 x0 = __ldg(xp + 0);
    float4 x1 = __ldg(xp + 1);

    for (int bi = 0; bi < 32; bi++) {
        float4 nx0, nx1;
        if (bi < 31) {
            const float4* nxp = (const float4*)(x + ((size_t)(b0 + bi + 1) * II + i) * PP);
            nx0 = __ldg(nxp + 0);
            nx1 = __ldg(nxp + 1);
        }
        __half* vout = g_votes + ((size_t)(b0 + bi) * II + i) * JD;
#pragma unroll
        for (int k = 0; k < 5; k++) {
            float acc =
                fmaf(wv0[k].x, x0.x,
                fmaf(wv0[k].y, x0.y,
                fmaf(wv0[k].z, x0.z,
                fmaf(wv0[k].w, x0.w,
                fmaf(wv1[k].x, x1.x,
                fmaf(wv1[k].y, x1.y,
                fmaf(wv1[k].z, x1.z, wv1[k].w * x1.w)))))));
            vout[lane + 32 * k] = __float2half_rn(acc);
            s_part[wid][lane + 32 * k] = acc;
        }
        __syncthreads();
        if (threadIdx.x < JD) {
            float s = 0.0f;
#pragma unroll
            for (int w = 0; w < 8; w++) s += s_part[w][threadIdx.x];
            atomicAdd(&g_s[0][(size_t)(b0 + bi) * JD + threadIdx.x], 0.1f * s);
        }
        __syncthreads();
        x0 = nx0; x1 = nx1;
    }
}

// ---------------------------------------------------------------------------
// Routing pass MODE (1 or 2). b0=0 so logits are votes.(v0[+v1]):
//   MODE 1: vp = squash(s0);              c = softmax_j(votes.vp); acc -> s1
//   MODE 2: vp = squash(s0) + squash(s1); c = softmax_j(votes.vp); acc -> s2
// Grid (9, 256): x = 128-i chunk, y = batch. 256 threads.
// Phase 1 (tid<128): thread owns one i — loads its 320B vote row once (10 x
//   256-bit LDG -> SMEM + registers), 10 dots + register-local softmax.
// Phase 2 (tid<160): thread owns (j,d) — sum_i c[i,j]*v[i,j,d] from SMEM,
//   one global atomicAdd per thread.
// ---------------------------------------------------------------------------
template <int MODE>
__global__ __launch_bounds__(256) void route_kernel() {
    __shared__ __half v_sm[CI * VS];                // 43008 B
    __shared__ float  c_sm[CI * JJ];                // 5120 B
    __shared__ __align__(16) float vp_s[JD];        // 640 B

    int b    = blockIdx.y;
    int chnk = blockIdx.x;
    int tid  = threadIdx.x;

    // ---- fused squash of previous s -> vp (160 threads, shfl_xor width 16) --
    if (tid < JD) {
        float s0 = g_s[0][b * JD + tid];
        float nn = s0 * s0;
#pragma unroll
        for (int o = 8; o; o >>= 1) nn += __shfl_xor_sync(0xffffffffu, nn, o, 16);
        float vp = s0 * (nn / (1.0f + nn) / sqrtf(nn + 1e-7f));
        if (MODE == 2) {
            float s1 = g_s[1][b * JD + tid];
            float n1 = s1 * s1;
#pragma unroll
            for (int o = 8; o; o >>= 1) n1 += __shfl_xor_sync(0xffffffffu, n1, o, 16);
            vp += s1 * (n1 / (1.0f + n1) / sqrtf(n1 + 1e-7f));
        }
        vp_s[tid] = vp;
    }
    __syncthreads();

    // ---- phase 1: per-i dots + register-local softmax (no shuffles) ----
    if (tid < CI) {
        const u64x4* src =
            (const u64x4*)(g_votes + ((size_t)b * II + chnk * CI + tid) * JD);
        float bnew[JJ];
#pragma unroll
        for (int j = 0; j < JJ; j++) {
            u64x4 a = (MODE == 2) ? ldg256_ef(src + j) : ldg256_el(src + j);
            // spill to smem for phase 2 (two 16B stores; 336B row stride)
            uint4* dst = (uint4*)(v_sm + tid * VS + j * DD);
            dst[0] = make_uint4((unsigned)(a.x), (unsigned)(a.x >> 32),
                                (unsigned)(a.y), (unsigned)(a.y >> 32));
            dst[1] = make_uint4((unsigned)(a.z), (unsigned)(a.z >> 32),
                                (unsigned)(a.w), (unsigned)(a.w >> 32));
            const __half2* h = (const __half2*)&a;
            const float4* vpf = (const float4*)(vp_s + j * DD);
            float4 p0 = vpf[0], p1 = vpf[1], p2 = vpf[2], p3 = vpf[3];
            float dot = 0.0f;
            float2 f;
            f = __half22float2(h[0]); dot = fmaf(f.x, p0.x, fmaf(f.y, p0.y, dot));
            f = __half22float2(h[1]); dot = fmaf(f.x, p0.z, fmaf(f.y, p0.w, dot));
            f = __half22float2(h[2]); dot = fmaf(f.x, p1.x, fmaf(f.y, p1.y, dot));
            f = __half22float2(h[3]); dot = fmaf(f.x, p1.z, fmaf(f.y, p1.w, dot));
            f = __half22float2(h[4]); dot = fmaf(f.x, p2.x, fmaf(f.y, p2.y, dot));
            f = __half22float2(h[5]); dot = fmaf(f.x, p2.z, fmaf(f.y, p2.w, dot));
            f = __half22float2(h[6]); dot = fmaf(f.x, p3.x, fmaf(f.y, p3.y, dot));
            f = __half22float2(h[7]); dot = fmaf(f.x, p3.z, fmaf(f.y, p3.w, dot));
            bnew[j] = dot;
        }
        float m = bnew[0];
#pragma unroll
        for (int j = 1; j < JJ; j++) m = fmaxf(m, bnew[j]);
        float sum = 0.0f;
#pragma unroll
        for (int j = 0; j < JJ; j++) { bnew[j] = expf(bnew[j] - m); sum += bnew[j]; }
        float r = 1.0f / sum;
#pragma unroll
        for (int j = 0; j < JJ; j++) c_sm[tid * JJ + j] = bnew[j] * r;
    }
    __syncthreads();

    // ---- phase 2: s[j,d] = sum_i c[i,j] * v[i,j,d] ----
    if (tid < JD) {
        int j = tid >> 4, d = tid & 15;
        const __half* vv = v_sm + j * DD + d;
        const float*  cc = c_sm + j;
        float acc = 0.0f;
#pragma unroll 8
        for (int i = 0; i < CI; i++)
            acc = fmaf(cc[i * JJ], __half2float(vv[i * VS]), acc);
        atomicAdd(&g_s[MODE][b * JD + tid], acc);
    }
}

// ---------------------------------------------------------------------------
// Final squash -> d_out
// ---------------------------------------------------------------------------
__global__ void squash_kernel(const float* __restrict__ s, float* __restrict__ out) {
    int t = blockIdx.x * blockDim.x + threadIdx.x;
    if (t >= BB * JJ) return;
    const float* sp = s + t * DD;
    float v[DD];
    float s2 = 0.0f;
#pragma unroll
    for (int d = 0; d < DD; d++) { v[d] = sp[d]; s2 = fmaf(v[d], v[d], s2); }
    float scale = s2 / (1.0f + s2) / sqrtf(s2 + 1e-7f);
#pragma unroll
    for (int d = 0; d < DD; d++) out[t * DD + d] = v[d] * scale;
}

// ---------------------------------------------------------------------------
extern "C" void kernel_launch(void* const* d_in, const int* in_sizes, int n_in,
                              void* d_out, int out_size) {
    const float* x = (const float*)d_in[0];   // [256,1152,8]
    const float* W = (const float*)d_in[1];   // [1152,10,16,8]
    float* out = (float*)d_out;               // [256,10,16]

    float* gs = nullptr;
    cudaGetSymbolAddress((void**)&gs, g_s);

    dim3 vgrid(II / 8, 8);
    dim3 rgrid(NCHUNK, BB);

    zero_kernel<<<(3 * BB * JD + 255) / 256, 256>>>();
    votes_kernel<<<vgrid, 256>>>(x, W);   // writes g_votes, accumulates s0

    route_kernel<1><<<rgrid, 256>>>();    // s1
    route_kernel<2><<<rgrid, 256>>>();    // s2

    squash_kernel<<<(BB * JJ + 255) / 256, 256>>>(gs + 2 * BB * JD, out);
}

// round 6
// speedup vs baseline: 2.5585x; 1.0473x over previous
#include <cuda_runtime.h>
#include <cuda_fp16.h>
#include <math.h>

// Problem dims
#define BB 256
#define II 1152
#define PP 8
#define JJ 10
#define DD 16
#define JD 160   // JJ*DD

// Route-kernel tiling: 4 warps/CTA, warp owns 32 i's -> 128 i per CTA
#define NCHUNK 9          // 1152 / 128
#define VS 168            // smem halves per i row (336B: 21 16B-slots -> conflict-free)
#define CS 10             // c floats per i row

// Scratch (device globals; no runtime allocation allowed)
__device__ __half g_votes[(size_t)BB * II * JD];  // 94.4 MB fp16
__device__ float  g_s[3][BB * JD];                // s0, s1, s2 accumulators

// 32-byte vector for 256-bit loads
struct __align__(32) u64x4 { unsigned long long x, y, z, w; };

__device__ __forceinline__ u64x4 ldg256_el(const u64x4* p) {
    u64x4 v;
    asm volatile("ld.global.nc.L2::evict_last.v4.u64 {%0,%1,%2,%3}, [%4];"
                 : "=l"(v.x), "=l"(v.y), "=l"(v.z), "=l"(v.w) : "l"(p));
    return v;
}
__device__ __forceinline__ u64x4 ldg256_ef(const u64x4* p) {
    u64x4 v;
    asm volatile("ld.global.nc.L2::evict_first.v4.u64 {%0,%1,%2,%3}, [%4];"
                 : "=l"(v.x), "=l"(v.y), "=l"(v.z), "=l"(v.w) : "l"(p));
    return v;
}

// ---------------------------------------------------------------------------
__global__ void zero_kernel() {
    int t = blockIdx.x * blockDim.x + threadIdx.x;
    if (t < 3 * BB * JD) ((float*)g_s)[t] = 0.0f;
}

// ---------------------------------------------------------------------------
// votes[b,i,jd] = sum_p W[i,jd,p] * x[b,i,p], stored fp16.
// Fuses iteration-0 routing: s0[b,jd] = 0.1 * sum_i votes[b,i,jd].
// Grid (144, 8): x = i-block of 8 (warp per i), y = batch-group of 32.
// ---------------------------------------------------------------------------
__global__ __launch_bounds__(256) void votes_kernel(const float* __restrict__ x,
                                                    const float* __restrict__ W) {
    __shared__ float s_part[8][JD];

    int wid  = threadIdx.x >> 5;
    int lane = threadIdx.x & 31;
    int i    = blockIdx.x * 8 + wid;
    int b0   = blockIdx.y * 32;

    const float4* Wp = (const float4*)(W + (size_t)i * (JD * PP));
    float4 wv0[5], wv1[5];
#pragma unroll
    for (int k = 0; k < 5; k++) {
        int jd = lane + 32 * k;
        wv0[k] = Wp[jd * 2 + 0];
        wv1[k] = Wp[jd * 2 + 1];
    }

    const float4* xp = (const float4*)(x + ((size_t)b0 * II + i) * PP);
    float4 x0 = __ldg(xp + 0);
    float4 x1 = __ldg(xp + 1);

    for (int bi = 0; bi < 32; bi++) {
        float4 nx0, nx1;
        if (bi < 31) {
            const float4* nxp = (const float4*)(x + ((size_t)(b0 + bi + 1) * II + i) * PP);
            nx0 = __ldg(nxp + 0);
            nx1 = __ldg(nxp + 1);
        }
        __half* vout = g_votes + ((size_t)(b0 + bi) * II + i) * JD;
#pragma unroll
        for (int k = 0; k < 5; k++) {
            float acc =
                fmaf(wv0[k].x, x0.x,
                fmaf(wv0[k].y, x0.y,
                fmaf(wv0[k].z, x0.z,
                fmaf(wv0[k].w, x0.w,
                fmaf(wv1[k].x, x1.x,
                fmaf(wv1[k].y, x1.y,
                fmaf(wv1[k].z, x1.z, wv1[k].w * x1.w)))))));
            vout[lane + 32 * k] = __float2half_rn(acc);
            s_part[wid][lane + 32 * k] = acc;
        }
        __syncthreads();
        if (threadIdx.x < JD) {
            float s = 0.0f;
#pragma unroll
            for (int w = 0; w < 8; w++) s += s_part[w][threadIdx.x];
            atomicAdd(&g_s[0][(size_t)(b0 + bi) * JD + threadIdx.x], 0.1f * s);
        }
        __syncthreads();
        x0 = nx0; x1 = nx1;
    }
}

// ---------------------------------------------------------------------------
// Warp-autonomous routing pass MODE (1 or 2). b0=0 so logits = votes.(v0[+v1]).
// Grid (9, 256), 128 threads (4 warps). Each warp independently processes a
// 32-i tile: pass A (lane=i): 10x 256-bit LDG (5 in flight), dot vs vp,
// register-local softmax, rows spilled to warp-private smem; pass B (lane
// owns 5 jd outputs): 32-i smem sweep, 5 global atomicAdds. No CTA barriers
// in the hot path.
// ---------------------------------------------------------------------------
template <int MODE>
__global__ __launch_bounds__(128) void route_kernel() {
    __shared__ __half v_sm[4][32 * VS];             // 4 x 10752 B
    __shared__ float  c_sm[4][32 * CS];             // 4 x 1280 B
    __shared__ __align__(16) float vp_s[JD];        // 640 B

    int b    = blockIdx.y;
    int chnk = blockIdx.x;
    int tid  = threadIdx.x;
    int w    = tid >> 5;
    int lane = tid & 31;

    // ---- vp = squash(s0) [+ squash(s1)] : warp 0, lane j ----
    if (tid < 32 && lane < JJ) {
        const float4* s0p = (const float4*)(&g_s[0][b * JD + lane * DD]);
        float4 a0 = s0p[0], a1 = s0p[1], a2 = s0p[2], a3 = s0p[3];
        float nn = a0.x*a0.x + a0.y*a0.y + a0.z*a0.z + a0.w*a0.w
                 + a1.x*a1.x + a1.y*a1.y + a1.z*a1.z + a1.w*a1.w
                 + a2.x*a2.x + a2.y*a2.y + a2.z*a2.z + a2.w*a2.w
                 + a3.x*a3.x + a3.y*a3.y + a3.z*a3.z + a3.w*a3.w;
        float sc = nn / (1.0f + nn) / sqrtf(nn + 1e-7f);
        float vp[DD];
        vp[0]=a0.x*sc; vp[1]=a0.y*sc; vp[2]=a0.z*sc; vp[3]=a0.w*sc;
        vp[4]=a1.x*sc; vp[5]=a1.y*sc; vp[6]=a1.z*sc; vp[7]=a1.w*sc;
        vp[8]=a2.x*sc; vp[9]=a2.y*sc; vp[10]=a2.z*sc; vp[11]=a2.w*sc;
        vp[12]=a3.x*sc; vp[13]=a3.y*sc; vp[14]=a3.z*sc; vp[15]=a3.w*sc;
        if (MODE == 2) {
            const float4* s1p = (const float4*)(&g_s[1][b * JD + lane * DD]);
            float4 c0 = s1p[0], c1 = s1p[1], c2 = s1p[2], c3 = s1p[3];
            float n1 = c0.x*c0.x + c0.y*c0.y + c0.z*c0.z + c0.w*c0.w
                     + c1.x*c1.x + c1.y*c1.y + c1.z*c1.z + c1.w*c1.w
                     + c2.x*c2.x + c2.y*c2.y + c2.z*c2.z + c2.w*c2.w
                     + c3.x*c3.x + c3.y*c3.y + c3.z*c3.z + c3.w*c3.w;
            float s1c = n1 / (1.0f + n1) / sqrtf(n1 + 1e-7f);
            vp[0]+=c0.x*s1c; vp[1]+=c0.y*s1c; vp[2]+=c0.z*s1c; vp[3]+=c0.w*s1c;
            vp[4]+=c1.x*s1c; vp[5]+=c1.y*s1c; vp[6]+=c1.z*s1c; vp[7]+=c1.w*s1c;
            vp[8]+=c2.x*s1c; vp[9]+=c2.y*s1c; vp[10]+=c2.z*s1c; vp[11]+=c2.w*s1c;
            vp[12]+=c3.x*s1c; vp[13]+=c3.y*s1c; vp[14]+=c3.z*s1c; vp[15]+=c3.w*s1c;
        }
#pragma unroll
        for (int d = 0; d < DD; d++) vp_s[lane * DD + d] = vp[d];
    }
    __syncthreads();

    // ---- pass A: lane = i, 10 dots + register-local softmax ----
    int i_glob = chnk * 128 + w * 32 + lane;
    const u64x4* src = (const u64x4*)(g_votes + ((size_t)b * II + i_glob) * JD);
    __half* vrow = &v_sm[w][lane * VS];
    float bnew[JJ];

#pragma unroll
    for (int g = 0; g < 2; g++) {
        u64x4 r[5];
#pragma unroll
        for (int j5 = 0; j5 < 5; j5++)
            r[j5] = (MODE == 2) ? ldg256_ef(src + g * 5 + j5)
                                : ldg256_el(src + g * 5 + j5);
#pragma unroll
        for (int j5 = 0; j5 < 5; j5++) {
            int j = g * 5 + j5;
            u64x4 a = r[j5];
            uint4* dst = (uint4*)(vrow + j * DD);
            dst[0] = make_uint4((unsigned)(a.x), (unsigned)(a.x >> 32),
                                (unsigned)(a.y), (unsigned)(a.y >> 32));
            dst[1] = make_uint4((unsigned)(a.z), (unsigned)(a.z >> 32),
                                (unsigned)(a.w), (unsigned)(a.w >> 32));
            const __half2* h = (const __half2*)&a;
            const float4* vpf = (const float4*)(vp_s + j * DD);
            float4 p0 = vpf[0], p1 = vpf[1], p2 = vpf[2], p3 = vpf[3];
            float dot = 0.0f;
            float2 f;
            f = __half22float2(h[0]); dot = fmaf(f.x, p0.x, fmaf(f.y, p0.y, dot));
            f = __half22float2(h[1]); dot = fmaf(f.x, p0.z, fmaf(f.y, p0.w, dot));
            f = __half22float2(h[2]); dot = fmaf(f.x, p1.x, fmaf(f.y, p1.y, dot));
            f = __half22float2(h[3]); dot = fmaf(f.x, p1.z, fmaf(f.y, p1.w, dot));
            f = __half22float2(h[4]); dot = fmaf(f.x, p2.x, fmaf(f.y, p2.y, dot));
            f = __half22float2(h[5]); dot = fmaf(f.x, p2.z, fmaf(f.y, p2.w, dot));
            f = __half22float2(h[6]); dot = fmaf(f.x, p3.x, fmaf(f.y, p3.y, dot));
            f = __half22float2(h[7]); dot = fmaf(f.x, p3.z, fmaf(f.y, p3.w, dot));
            bnew[j] = dot;
        }
    }
    float m = bnew[0];
#pragma unroll
    for (int j = 1; j < JJ; j++) m = fmaxf(m, bnew[j]);
    float sum = 0.0f;
#pragma unroll
    for (int j = 0; j < JJ; j++) { bnew[j] = __expf(bnew[j] - m); sum += bnew[j]; }
    float rinv = 1.0f / sum;
#pragma unroll
    for (int j = 0; j < JJ; j++) c_sm[w][lane * CS + j] = bnew[j] * rinv;

    __syncwarp();

    // ---- pass B: lane owns jd = lane + 32q (q=0..4), sweep 32 i's ----
    float acc[5] = {0.0f, 0.0f, 0.0f, 0.0f, 0.0f};
    const __half* vbase = &v_sm[w][0];
    const float*  cbase = &c_sm[w][0];
#pragma unroll 4
    for (int i = 0; i < 32; i++) {
#pragma unroll
        for (int q = 0; q < 5; q++) {
            int jd = lane + 32 * q;
            int j  = jd >> 4;
            acc[q] = fmaf(cbase[i * CS + j],
                          __half2float(vbase[i * VS + jd]), acc[q]);
        }
    }
#pragma unroll
    for (int q = 0; q < 5; q++)
        atomicAdd(&g_s[MODE][b * JD + lane + 32 * q], acc[q]);
}

// ---------------------------------------------------------------------------
__global__ void squash_kernel(const float* __restrict__ s, float* __restrict__ out) {
    int t = blockIdx.x * blockDim.x + threadIdx.x;
    if (t >= BB * JJ) return;
    const float* sp = s + t * DD;
    float v[DD];
    float s2 = 0.0f;
#pragma unroll
    for (int d = 0; d < DD; d++) { v[d] = sp[d]; s2 = fmaf(v[d], v[d], s2); }
    float scale = s2 / (1.0f + s2) / sqrtf(s2 + 1e-7f);
#pragma unroll
    for (int d = 0; d < DD; d++) out[t * DD + d] = v[d] * scale;
}

// ---------------------------------------------------------------------------
extern "C" void kernel_launch(void* const* d_in, const int* in_sizes, int n_in,
                              void* d_out, int out_size) {
    const float* x = (const float*)d_in[0];   // [256,1152,8]
    const float* W = (const float*)d_in[1];   // [1152,10,16,8]
    float* out = (float*)d_out;               // [256,10,16]

    float* gs = nullptr;
    cudaGetSymbolAddress((void**)&gs, g_s);

    dim3 vgrid(II / 8, 8);
    dim3 rgrid(NCHUNK, BB);

    zero_kernel<<<(3 * BB * JD + 255) / 256, 256>>>();
    votes_kernel<<<vgrid, 256>>>(x, W);   // writes g_votes, accumulates s0

    route_kernel<1><<<rgrid, 128>>>();    // s1
    route_kernel<2><<<rgrid, 128>>>();    // s2

    squash_kernel<<<(BB * JJ + 255) / 256, 256>>>(gs + 2 * BB * JD, out);
}